// round 17
// baseline (speedup 1.0000x reference)
#include <cuda_runtime.h>
#include <math.h>

#define BS   512
#define MM   8
#define TT   2048
#define NS   2047
#define NCH  32
#define CL   64
#define SUB  8
#define CONV_EPS 4e-3f

#define S20(r,c) ((r)*20+(c))
#define S12(r,c) ((r)*12+(c))

// Packed maps: W1[t]=[M;G;0] (32x16), W2[t]=[N;D;0] (32x8); rows 24-31 stay 0.
__device__ float g_W1[(size_t)NS * 512];
__device__ float g_W2[(size_t)NS * 256];
__device__ float g_F[1024];            // fused frozen rows [32][32]
__device__ float g_P[NS * 128];
__device__ float g_T[NCH * 8 * 256];
__device__ float g_GS[NCH * 8 * 256];
__device__ float g_A[NCH * 256];
__device__ float g_b[BS * NCH * 16];
__device__ float g_m0[BS * NCH * 16];
__device__ int   g_tc;
__device__ int   g_nan[BS];            // OR-accumulated; inputs fixed per graph

__device__ __forceinline__ float dot16(const float* a, const float* b) {
    const float4* A = (const float4*)a; const float4* B = (const float4*)b;
    float4 a0=A[0],a1=A[1],a2=A[2],a3=A[3], b0=B[0],b1=B[1],b2=B[2],b3=B[3];
    float s0=a0.x*b0.x+a0.y*b0.y+a0.z*b0.z+a0.w*b0.w;
    float s1=a1.x*b1.x+a1.y*b1.y+a1.z*b1.z+a1.w*b1.w;
    float s2=a2.x*b2.x+a2.y*b2.y+a2.z*b2.z+a2.w*b2.w;
    float s3=a3.x*b3.x+a3.y*b3.y+a3.z*b3.z+a3.w*b3.w;
    return (s0+s1)+(s2+s3);
}
// register-row x smem-row dot; identical accumulation order to dot16
__device__ __forceinline__ float dot16r(const float* fr, const float* b) {
    const float4* B = (const float4*)b;
    float4 b0=B[0],b1=B[1],b2=B[2],b3=B[3];
    float s0=fr[0]*b0.x+fr[1]*b0.y+fr[2]*b0.z+fr[3]*b0.w;
    float s1=fr[4]*b1.x+fr[5]*b1.y+fr[6]*b1.z+fr[7]*b1.w;
    float s2=fr[8]*b2.x+fr[9]*b2.y+fr[10]*b2.z+fr[11]*b2.w;
    float s3=fr[12]*b3.x+fr[13]*b3.y+fr[14]*b3.z+fr[15]*b3.w;
    return (s0+s1)+(s2+s3);
}
__device__ __forceinline__ float dot8(const float* a, const float* b) {
    const float4* A = (const float4*)a; const float4* B = (const float4*)b;
    float4 a0=A[0],a1=A[1], b0=B[0],b1=B[1];
    return (a0.x*b0.x+a0.y*b0.y+a0.z*b0.z+a0.w*b0.w)
         + (a1.x*b1.x+a1.y*b1.y+a1.z*b1.z+a1.w*b1.w);
}

// ---------------------------------------------------------------------------
// Phase 1: Riccati, 4 barriers/step, F rows cached in registers for the
// crossbar-expensive stages (Y, FP).
//  s0: HC = H*cov (+deferred G store)      | X = F*cov
//  s1: S = HC*H^T + R | FP = F*HC^T (reg F) | Y rows 0-3 (reg F)
//  s2: warp0 augmented GJ [S|FP^T] -> Nn    | Y rows 4-15 (reg F)
//  s3: cov' update ; M,N,D stores ; conv-or
// ---------------------------------------------------------------------------
__global__ void __launch_bounds__(256) phase1_kernel(
        const float* __restrict__ F_, const float* __restrict__ H_,
        const float* __restrict__ Q_, const float* __restrict__ R_) {
    __shared__ __align__(16) float sF[320], cov[320], X[320], Y[320];
    __shared__ __align__(16) float sH[160], sHF[160], HC[160], NnT[160], Gf[160];
    __shared__ __align__(16) float sHT[192], FP[192], Nn[192];
    __shared__ __align__(16) float D[96];
    __shared__ float W[64], sQ[256], sR[64];

    int tid = threadIdx.x;
    int i = tid >> 4, j = tid & 15;
    sF[S20(i, j)] = F_[tid];
    sQ[tid] = Q_[tid];
    if (tid < 128) sH[S20(tid >> 4, tid & 15)] = H_[tid];
    if (tid < 64)  sR[tid] = R_[tid];
    cov[S20(i, j)] = (i == j) ? 1.f : 0.f;
    __syncthreads();
    if (tid < 128) {
        int jj = tid >> 3, aa = tid & 7;
        sHT[S12(jj, aa)] = sH[S20(aa, jj)];
    } else {
        int u = tid - 128, aa = u >> 4, jj = u & 15;
        float s = 0.f;
        #pragma unroll
        for (int e = 0; e < 16; e++) s += sH[S20(aa, e)] * sF[S20(e, jj)];
        sHF[S20(aa, jj)] = s;
    }
    __syncthreads();

    // per-thread fixed F rows (constant across all steps)
    float FD[16], FE[16], FC16[16];
    {
        int rd = (tid - 192) & 15;          // s1 Y stage row
        int re = (tid + 32) & 15;           // s2 Y stage row
        int rc = ((tid - 64) >> 3) & 15;    // s1 FP stage row
        #pragma unroll
        for (int e = 0; e < 16; e++) {
            FD[e]   = sF[S20(rd, e)];
            FE[e]   = sF[S20(re, e)];
            FC16[e] = sF[S20(rc, e)];
        }
    }

    int tc = NS;
    for (int t = 0; t < NS; t++) {
        // ---- s0
        if (tid < 128) {
            int a = tid >> 4, c = tid & 15;
            HC[S20(a, c)] = dot16(&sH[S20(a, 0)], &cov[S20(c, 0)]);
            if (t > 0)
                g_W1[(size_t)(t - 1) * 512 + 256 + tid] =
                    sHF[S20(a, c)] - dot8(&D[S12(a, 0)], &sHT[S12(c, 0)]);
        } else {
            int u = tid - 128, r = u >> 4, c = u & 15;
            X[S20(r, c)]     = dot16(&sF[S20(r, 0)],     &cov[S20(c, 0)]);
            X[S20(r + 8, c)] = dot16(&sF[S20(r + 8, 0)], &cov[S20(c, 0)]);
        }
        __syncthreads();
        // ---- s1
        if (tid < 64) {
            int a = tid >> 3, c = tid & 7;
            W[a * 8 + c] = sR[a * 8 + c] + dot16(&HC[S20(a, 0)], &sH[S20(c, 0)]);
        } else if (tid < 192) {
            int u = tid - 64, r = u >> 3, cc = u & 7;
            FP[S12(r, cc)] = dot16r(FC16, &HC[S20(cc, 0)]);
        } else {
            int u = tid - 192;                 // Y outputs 0..63 (rows 0-3)
            Y[S20(u >> 4, u & 15)] = dot16r(FD, &X[S20(u >> 4, 0)]);
        }
        __syncthreads();
        // ---- s2: warp0 augmented GJ ; others Y rows 4-15
        if (tid < 32) {
            int lane = tid;
            float w[8];
            if (lane < 8) {
                #pragma unroll
                for (int r = 0; r < 8; r++) w[r] = W[r * 8 + lane];
            } else {
                int jj = (lane - 8) & 15;
                #pragma unroll
                for (int r = 0; r < 8; r++) w[r] = FP[S12(jj, r)];
            }
            #pragma unroll
            for (int k = 0; k < 8; k++) {
                float a[8];
                #pragma unroll
                for (int r = 0; r < 8; r++)
                    a[r] = __shfl_sync(0xffffffffu, w[r], k);
                float rp = __fdividef(1.0f, a[k]);
                w[k] *= rp;
                #pragma unroll
                for (int r = 0; r < 8; r++)
                    if (r != k) w[r] -= a[r] * w[k];
            }
            if (lane >= 8 && lane < 24) {
                int jj = lane - 8;
                #pragma unroll
                for (int a2 = 0; a2 < 8; a2++) {
                    Nn[S12(jj, a2)] = w[a2];
                    NnT[S20(a2, jj)] = w[a2];
                }
            }
        } else if (tid < 224) {
            int u = tid - 32 + 64;               // Y outputs 64..255
            Y[S20(u >> 4, u & 15)] = dot16r(FE, &X[S20(u >> 4, 0)]);
        }
        __syncthreads();
        // ---- s3: cov update + M/N/D stores + convergence
        float cnew;
        {
            float t1 = dot8(&Nn[S12(i, 0)], &FP[S12(j, 0)]);
            float t2 = dot8(&FP[S12(i, 0)], &Nn[S12(j, 0)]);
            float m  = sF[S20(i, j)] - dot8(&Nn[S12(i, 0)], &sHT[S12(j, 0)]);
            cnew = Y[S20(i, j)] + sQ[tid] - 0.5f * (t1 + t2);
            g_W1[(size_t)t * 512 + tid] = m;
        }
        if (tid < 128) {
            g_W2[(size_t)t * 256 + tid] = Nn[S12(tid >> 3, tid & 7)];
        } else if (tid < 192) {
            int u = tid - 128, a = u >> 3, bb = u & 7;
            float d = dot16(&sH[S20(a, 0)], &NnT[S20(bb, 0)]);
            D[S12(a, bb)] = d;
            g_W2[(size_t)t * 256 + 128 + u] = d;
        }
        float oldc = cov[S20(i, j)];
        float dlt = fabsf(cnew - oldc);
        cov[S20(i, j)] = cnew;
        int any = __syncthreads_or(dlt > CONV_EPS * (fabsf(oldc) + 1e-2f));
        if (!any) { tc = t + 1; break; }
    }
    if (tid == 0) g_tc = tc;
    if (tid < 128) {
        int a = tid >> 4, c = tid & 15;
        float gv = sHF[S20(a, c)] - dot8(&D[S12(a, 0)], &sHT[S12(c, 0)]);
        g_W1[(size_t)(tc - 1) * 512 + 256 + tid] = gv;
        Gf[S20(a, c)] = gv;
    }
    __syncthreads();
    // fused frozen 2-step table: rows 0-15 [M^2|MN|N], 16-23 [G|D|0], 24-31 [GM|GN|D]
    for (int idx = tid; idx < 1024; idx += 256) {
        int r = idx >> 5, cc = idx & 31;
        float v = 0.f;
        if (r < 16) {
            if (cc < 16) {
                #pragma unroll
                for (int e = 0; e < 16; e++) {
                    float mre = sF[S20(r, e)] - dot8(&Nn[S12(r, 0)], &sHT[S12(e, 0)]);
                    float mec = sF[S20(e, cc)] - dot8(&Nn[S12(e, 0)], &sHT[S12(cc, 0)]);
                    v += mre * mec;
                }
            } else if (cc < 24) {
                #pragma unroll
                for (int e = 0; e < 16; e++) {
                    float mre = sF[S20(r, e)] - dot8(&Nn[S12(r, 0)], &sHT[S12(e, 0)]);
                    v += mre * Nn[S12(e, cc - 16)];
                }
            } else {
                v = Nn[S12(r, cc - 24)];
            }
        } else if (r < 24) {
            int jj = r - 16;
            if (cc < 16) v = Gf[S20(jj, cc)];
            else if (cc < 24) v = D[S12(jj, cc - 16)];
        } else {
            int jj = r - 24;
            if (cc < 16) {
                #pragma unroll
                for (int e = 0; e < 16; e++) {
                    float mec = sF[S20(e, cc)] - dot8(&Nn[S12(e, 0)], &sHT[S12(cc, 0)]);
                    v += Gf[S20(jj, e)] * mec;
                }
            } else if (cc < 24) {
                #pragma unroll
                for (int e = 0; e < 16; e++) v += Gf[S20(jj, e)] * Nn[S12(e, cc - 16)];
            } else {
                v = D[S12(jj, cc - 24)];
            }
        }
        g_F[idx] = v;
    }
}

// 3a: per-(chunk,group) 8-step serial suffix (clamped reads)
__global__ void __launch_bounds__(256) group_serial_kernel() {
    int c = blockIdx.x >> 3, g = blockIdx.x & 7;
    int base = c * CL + g * 8;
    int n = NS - base; if (n > 8) n = 8;
    int tcl = g_tc - 1;
    __shared__ float S[2][256], Mt[256], Nt[128];
    int tid = threadIdx.x;
    int i = tid >> 4, j = tid & 15;
    S[0][tid] = (i == j) ? 1.f : 0.f;
    int par = 0;
    int ts = base + n - 1; if (ts > tcl) ts = tcl;
    float mreg = g_W1[(size_t)ts * 512 + tid];
    float nreg = (tid < 128) ? g_W2[(size_t)ts * 256 + tid] : 0.f;
    __syncthreads();
    for (int it = n - 1; it >= 0; --it) {
        Mt[tid] = mreg;
        if (tid < 128) Nt[tid] = nreg;
        __syncthreads();
        if (it > 0) {
            int t2 = base + it - 1; if (t2 > tcl) t2 = tcl;
            mreg = g_W1[(size_t)t2 * 512 + tid];
            if (tid < 128) nreg = g_W2[(size_t)t2 * 256 + tid];
        }
        if (tid < 128) {
            int r = tid >> 3, cc = tid & 7;
            float s = 0.f;
            #pragma unroll
            for (int e = 0; e < 16; e++) s += S[par][r * 16 + e] * Nt[e * 8 + cc];
            g_P[(base + it) * 128 + tid] = s;
        }
        float sn = 0.f;
        #pragma unroll
        for (int e = 0; e < 16; e++) sn += S[par][i * 16 + e] * Mt[e * 16 + j];
        S[par ^ 1][tid] = sn;
        __syncthreads();
        par ^= 1;
    }
    g_T[(c * 8 + g) * 256 + tid] = S[par][tid];
}

// 3b: per-chunk scan of 8 group products -> GS_g, A_c   (32 blocks)
__global__ void __launch_bounds__(256) group_scan_kernel() {
    int c = blockIdx.x;
    __shared__ float S[2][256], Tt[256];
    int tid = threadIdx.x;
    int i = tid >> 4, j = tid & 15;
    S[0][tid] = (i == j) ? 1.f : 0.f;
    int par = 0;
    for (int g = 7; g >= 0; --g) {
        Tt[tid] = g_T[(c * 8 + g) * 256 + tid];
        __syncthreads();
        float v = 0.f;
        #pragma unroll
        for (int e = 0; e < 16; e++) v += S[par][i * 16 + e] * Tt[e * 16 + j];
        S[par ^ 1][tid] = v;
        if (g >= 1) g_GS[(c * 8 + g) * 256 + tid] = v;
        __syncthreads();
        par ^= 1;
    }
    g_A[c * 256 + tid] = S[par][tid];
}

// 3c: apply GS_{g+1} to U (groups 0..6)   (224 parallel blocks)
__global__ void __launch_bounds__(256) apply_kernel() {
    int c = blockIdx.x / 7, g = blockIdx.x % 7;
    int base = c * CL + g * 8;
    __shared__ float GSs[256], Us[1024];
    int tid = threadIdx.x;
    GSs[tid] = g_GS[(c * 8 + g + 1) * 256 + tid];
    #pragma unroll
    for (int q = 0; q < 4; q++) {
        int k = tid + q * 256;
        Us[k] = g_P[(base + (k >> 7)) * 128 + (k & 127)];
    }
    __syncthreads();
    #pragma unroll
    for (int q = 0; q < 4; q++) {
        int k = tid + q * 256;
        int p = k >> 7, rc = k & 127, r = rc >> 3, cc = rc & 7;
        float v = 0.f;
        #pragma unroll
        for (int e = 0; e < 16; e++) v += GSs[r * 16 + e] * Us[p * 128 + e * 8 + cc];
        g_P[(base + p) * 128 + rc] = v;
    }
}

// Kernel 4: b_c = sum_t P_t * obs_t + folded NaN detection.
#define BGB 8
__global__ void __launch_bounds__(256) bvec_kernel(const float* __restrict__ x) {
    int c = blockIdx.x & (NCH - 1);
    int bg = blockIdx.x >> 5;
    int cstart = c * CL;
    int clen = (NS - cstart < CL) ? (NS - cstart) : CL;
    __shared__ __align__(16) float sP[CL * 128];
    __shared__ __align__(16) float sX[BGB][CL][8];
    __shared__ int nanf[BGB];
    int tid = threadIdx.x;
    if (tid < BGB) nanf[tid] = 0;
    for (int idx = tid; idx < clen * 128; idx += 256)
        sP[idx] = g_P[cstart * 128 + idx];
    for (int idx = tid; idx < BGB * 8 * clen; idx += 256) {
        int s = idx % clen;
        int bm = idx / clen;
        int m = bm & 7, b = bm >> 3;
        float v = x[((size_t)(bg * BGB + b) * MM + m) * TT + cstart + s];
        if (isnan(v)) atomicOr(&nanf[b], 1);
        sX[b][s][m] = v;
    }
    __syncthreads();
    if (tid < BGB && nanf[tid]) atomicOr(&g_nan[bg * BGB + tid], 1);
    int w = tid >> 5, lane = tid & 31;
    int b = bg * BGB + w;
    int row = lane & 15;
    float acc = 0.f;
    for (int s = (lane >> 4); s < clen; s += 2) {
        const float4* pp = (const float4*)&sP[s * 128 + row * 8];
        float4 p0 = pp[0], p1 = pp[1];
        const float4* op = (const float4*)&sX[w][s][0];
        float4 o0 = op[0], o1 = op[1];
        acc += p0.x*o0.x + p0.y*o0.y + p0.z*o0.z + p0.w*o0.w
             + p1.x*o1.x + p1.y*o1.y + p1.z*o1.z + p1.w*o1.w;
    }
    acc += __shfl_xor_sync(0xffffffffu, acc, 16);
    if (lane < 16) g_b[(b * NCH + c) * 16 + lane] = acc;
}

// Kernel 5: serial scan over 32 chunks; split-K across half-warps.
__global__ void __launch_bounds__(256) scan_kernel() {
    __shared__ float sA[NCH * 256];
    int tid = threadIdx.x;
    for (int idx = tid; idx < NCH * 256; idx += 256) sA[idx] = g_A[idx];
    __syncthreads();
    int w = tid >> 5, lane = tid & 31;
    int b = blockIdx.x * 8 + w;
    int row = lane & 15;
    int half8 = (lane >> 4) << 3;
    float mean_i = 0.f;
    float breg = (lane < 16) ? g_b[(b * NCH + 0) * 16 + lane] : 0.f;
    for (int c = 0; c < NCH; c++) {
        if (lane < 16) g_m0[(b * NCH + c) * 16 + lane] = mean_i;
        float bn = (lane < 16 && c + 1 < NCH) ? g_b[(b * NCH + c + 1) * 16 + lane] : 0.f;
        float nm = breg;
        #pragma unroll
        for (int e = 0; e < 8; e++) {
            float me = __shfl_sync(0xffffffffu, mean_i, half8 + e);
            nm += sA[c * 256 + row * 16 + half8 + e] * me;
        }
        nm += __shfl_xor_sync(0xffffffffu, nm, 16);
        mean_i = nm;
        breg = bn;
    }
}

// ---------------------------------------------------------------------------
// Kernel 6: within-chunk recursion + output (unchanged).
// ---------------------------------------------------------------------------
__global__ void __launch_bounds__(256) phase2b_kernel(const float* __restrict__ x,
                                                      float* __restrict__ out) {
    int c = blockIdx.x & (NCH - 1);
    int bg = blockIdx.x >> 5;
    int cstart = c * CL;
    int clen = (NS - cstart < CL) ? (NS - cstart) : CL;
    int tid = threadIdx.x, w = tid >> 5, lane = tid & 31;
    int b = bg * 8 + w;
    int tcl = g_tc;

    __shared__ __align__(16) float sB[8][32];

    if (cstart >= tcl) {
        const float* xb = x + (size_t)b * MM * TT;
        float* ob = out + (size_t)b * MM * TT;
        const float4* Fp = (const float4*)(g_F + lane * 32);
        float4 R0 = Fp[0], R1 = Fp[1], R2 = Fp[2], R3 = Fp[3];
        float4 R4 = Fp[4], R5 = Fp[5], R6 = Fp[6], R7 = Fp[7];

        if (lane < 16) sB[w][lane] = g_m0[(b * NCH + c) * 16 + lane];

        int m = lane & 7;
        int tend = cstart + clen;
        float nextobs = 0.f;
        if (lane >= 16)
            nextobs = xb[(size_t)m * TT + cstart + ((lane >= 24) ? 1 : 0)];

        int t = cstart;
        int nd = clen >> 1;
        for (int it = 0; it < nd; it++, t += 2) {
            if (lane >= 16) sB[w][lane] = nextobs;
            __syncwarp();
            const float4* bp = (const float4*)&sB[w][0];
            float4 m0 = bp[0], m1 = bp[1], m2 = bp[2], m3 = bp[3];
            float4 oa = bp[4], obv = bp[5], oc = bp[6], od = bp[7];
            if (lane >= 16) {
                int tn = t + 2 + ((lane >= 24) ? 1 : 0);
                if (tn < tend) nextobs = xb[(size_t)m * TT + tn];
            }
            float s0 = R0.x*m0.x + R0.y*m0.y + R0.z*m0.z + R0.w*m0.w;
            float s1 = R1.x*m1.x + R1.y*m1.y + R1.z*m1.z + R1.w*m1.w;
            float s2 = R2.x*m2.x + R2.y*m2.y + R2.z*m2.z + R2.w*m2.w;
            float s3 = R3.x*m3.x + R3.y*m3.y + R3.z*m3.z + R3.w*m3.w;
            float s4 = R4.x*oa.x + R4.y*oa.y + R4.z*oa.z + R4.w*oa.w;
            float s5 = R5.x*obv.x + R5.y*obv.y + R5.z*obv.z + R5.w*obv.w;
            float s6 = R6.x*oc.x + R6.y*oc.y + R6.z*oc.z + R6.w*oc.w;
            float s7 = R7.x*od.x + R7.y*od.y + R7.z*od.z + R7.w*od.w;
            float acc = ((s0 + s1) + (s2 + s3)) + ((s4 + s5) + (s6 + s7));

            if (lane >= 16)
                ob[(size_t)m * TT + t + ((lane >= 24) ? 2 : 1)] = acc;
            __syncwarp();
            if (lane < 16) sB[w][lane] = acc;
        }
        if (clen & 1) {
            if (lane >= 16) sB[w][lane] = nextobs;
            __syncwarp();
            const float4* bp = (const float4*)&sB[w][0];
            float4 m0 = bp[0], m1 = bp[1], m2 = bp[2], m3 = bp[3];
            float4 oa = bp[4], obv = bp[5], oc = bp[6], od = bp[7];
            float s0 = R0.x*m0.x + R0.y*m0.y + R0.z*m0.z + R0.w*m0.w;
            float s1 = R1.x*m1.x + R1.y*m1.y + R1.z*m1.z + R1.w*m1.w;
            float s2 = R2.x*m2.x + R2.y*m2.y + R2.z*m2.z + R2.w*m2.w;
            float s3 = R3.x*m3.x + R3.y*m3.y + R3.z*m3.z + R3.w*m3.w;
            float s4 = R4.x*oa.x + R4.y*oa.y + R4.z*oa.z + R4.w*oa.w;
            float s5 = R5.x*obv.x + R5.y*obv.y + R5.z*obv.z + R5.w*obv.w;
            float s6 = R6.x*oc.x + R6.y*oc.y + R6.z*oc.z + R6.w*oc.w;
            float s7 = R7.x*od.x + R7.y*od.y + R7.z*od.z + R7.w*od.w;
            float acc = ((s0 + s1) + (s2 + s3)) + ((s4 + s5) + (s6 + s7));
            if (lane >= 16 && lane < 24)
                ob[(size_t)m * TT + t + 1] = acc;
        }
        return;
    }

    // ---- transient smem path (clamped matrix reads) ----
    __shared__ __align__(16) float sW1[SUB][32][20];
    __shared__ __align__(16) float sW2[SUB][32][12];
    __shared__ __align__(16) float sX[8][SUB][8];
    __shared__ __align__(16) float sY[8][8][SUB];
    __shared__ __align__(16) float sMean[8][16];

    const size_t xbase = (size_t)b * MM * TT;
    if (lane < 16) sMean[w][lane] = g_m0[(b * NCH + c) * 16 + lane];
    if (c == 0 && lane < 8) out[xbase + (size_t)lane * TT] = 0.f;
    __syncwarp();

    for (int t0 = 0; t0 < clen; t0 += SUB) {
        int ns = (clen - t0 < SUB) ? (clen - t0) : SUB;
        __syncthreads();
        for (int idx = tid; idx < ns * 512; idx += 256) {
            int s = idx >> 9, rc = idx & 511;
            int ts = cstart + t0 + s; if (ts >= tcl) ts = tcl - 1;
            sW1[s][rc >> 4][rc & 15] = g_W1[(size_t)ts * 512 + rc];
        }
        for (int idx = tid; idx < ns * 256; idx += 256) {
            int s = idx >> 8, rc = idx & 255;
            int ts = cstart + t0 + s; if (ts >= tcl) ts = tcl - 1;
            sW2[s][rc >> 3][rc & 7] = g_W2[(size_t)ts * 256 + rc];
        }
        for (int idx = tid; idx < 64 * ns; idx += 256) {
            int s = idx % ns;
            int bm = idx / ns;
            int m = bm & 7, bb = bm >> 3;
            sX[bb][s][m] = x[((size_t)(bg * 8 + bb) * MM + m) * TT + cstart + t0 + s];
        }
        __syncthreads();

        for (int s = 0; s < ns; s++) {
            const float4* w1 = (const float4*)&sW1[s][lane][0];
            float4 a0 = w1[0], a1 = w1[1], a2 = w1[2], a3 = w1[3];
            const float4* w2 = (const float4*)&sW2[s][lane][0];
            float4 c0 = w2[0], c1 = w2[1];
            const float4* mp = (const float4*)&sMean[w][0];
            float4 m0 = mp[0], m1 = mp[1], m2 = mp[2], m3 = mp[3];
            const float4* op = (const float4*)&sX[w][s][0];
            float4 o0 = op[0], o1 = op[1];
            float s0 = a0.x*m0.x + a0.y*m0.y + a0.z*m0.z + a0.w*m0.w;
            float s1 = a1.x*m1.x + a1.y*m1.y + a1.z*m1.z + a1.w*m1.w;
            float s2 = a2.x*m2.x + a2.y*m2.y + a2.z*m2.z + a2.w*m2.w;
            float s3 = a3.x*m3.x + a3.y*m3.y + a3.z*m3.z + a3.w*m3.w;
            float s4 = c0.x*o0.x + c0.y*o0.y + c0.z*o0.z + c0.w*o0.w;
            float s5 = c1.x*o1.x + c1.y*o1.y + c1.z*o1.z + c1.w*o1.w;
            float acc = ((s0 + s1) + (s2 + s3)) + (s4 + s5);
            __syncwarp();
            if (lane < 16)      sMean[w][lane] = acc;
            else if (lane < 24) sY[w][lane - 16][s] = acc;
            __syncwarp();
        }
        __syncthreads();
        for (int idx = tid; idx < 64 * ns; idx += 256) {
            int s = idx % ns;
            int bm = idx / ns;
            int m = bm & 7, bb = bm >> 3;
            out[((size_t)(bg * 8 + bb) * MM + m) * TT + cstart + t0 + s + 1] = sY[bb][m][s];
        }
    }
}

// Kernel 7: exact per-batch fallback for NaN-containing batches
__global__ void slow_kernel(const float* __restrict__ x, const float* __restrict__ F_,
                            const float* __restrict__ H_, const float* __restrict__ Q_,
                            const float* __restrict__ R_, float* __restrict__ out) {
    int b = blockIdx.x;
    if (!g_nan[b]) return;
    int tid = threadIdx.x;
    __shared__ float sF[256], sH[128], sQ[256], sR[64];
    __shared__ float cov[256], covn[256], P[128], W[2][128], K[128], CU[256], FC[256];
    __shared__ float mean[16], meanu[16], meanp[16], obs[8], resid[8];
    __shared__ int nanb;

    sF[tid] = F_[tid];
    sQ[tid] = Q_[tid];
    if (tid < 128) sH[tid] = H_[tid];
    if (tid < 64)  sR[tid] = R_[tid];
    cov[tid] = ((tid >> 4) == (tid & 15)) ? 1.f : 0.f;
    if (tid < 16) mean[tid] = 0.f;
    if (tid < 8)  out[((size_t)b * MM + tid) * TT] = 0.f;
    __syncthreads();

    for (int t = 0; t < NS; t++) {
        if (tid == 0) {
            int nb = 0;
            for (int j = 0; j < 8; j++) {
                float v = x[((size_t)b * MM + j) * TT + t];
                if (isnan(v)) { nb = 1; v = 0.f; }
                obs[j] = v;
            }
            nanb = nb;
        }
        __syncthreads();
        if (tid < 128) {
            int i = tid >> 3, j = tid & 7;
            float s = 0.f;
            #pragma unroll
            for (int e = 0; e < 16; e++) s += cov[i * 16 + e] * sH[j * 16 + e];
            P[tid] = s;
        }
        if (tid >= 128 && tid < 136) {
            int j = tid - 128;
            float s = obs[j];
            #pragma unroll
            for (int e = 0; e < 16; e++) s -= sH[j * 16 + e] * mean[e];
            resid[j] = s;
        }
        __syncthreads();
        if (tid < 128) {
            int a = tid >> 4, c = tid & 15;
            float v;
            if (c < 8) {
                float s = sR[a * 8 + c];
                #pragma unroll
                for (int e = 0; e < 16; e++) s += sH[a * 16 + e] * P[e * 8 + c];
                v = s;
            } else v = (a == (c - 8)) ? 1.f : 0.f;
            W[0][a * 16 + c] = v;
        }
        __syncthreads();
        #pragma unroll 1
        for (int k = 0; k < 8; k++) {
            int cur = k & 1;
            if (tid < 128) {
                int a = tid >> 4, c = tid & 15;
                float piv = W[cur][k * 16 + k];
                float wkc = W[cur][k * 16 + c] / piv;
                W[cur ^ 1][a * 16 + c] = (a == k) ? wkc
                                                  : W[cur][a * 16 + c] - W[cur][a * 16 + k] * wkc;
            }
            __syncthreads();
        }
        if (tid < 128) {
            int i = tid >> 3, j = tid & 7;
            float s = 0.f;
            #pragma unroll
            for (int a = 0; a < 8; a++) s += P[i * 8 + a] * W[0][a * 16 + 8 + j];
            K[tid] = s;
        }
        __syncthreads();
        if (tid < 16) {
            float s = mean[tid];
            #pragma unroll
            for (int a = 0; a < 8; a++) s += K[tid * 8 + a] * resid[a];
            meanu[tid] = nanb ? mean[tid] : s;
        }
        {
            int i = tid >> 4, j = tid & 15;
            float s = cov[tid];
            #pragma unroll
            for (int a = 0; a < 8; a++) s -= K[i * 8 + a] * P[j * 8 + a];
            CU[tid] = nanb ? cov[tid] : s;
        }
        __syncthreads();
        {
            int i = tid >> 4, j = tid & 15;
            float s = 0.f;
            #pragma unroll
            for (int e = 0; e < 16; e++)
                s += sF[i * 16 + e] * 0.5f * (CU[e * 16 + j] + CU[j * 16 + e]);
            FC[tid] = s;
        }
        if (tid < 16) {
            float s = 0.f;
            #pragma unroll
            for (int e = 0; e < 16; e++) s += sF[tid * 16 + e] * meanu[e];
            meanp[tid] = s;
        }
        __syncthreads();
        {
            int i = tid >> 4, j = tid & 15;
            float s = sQ[tid];
            #pragma unroll
            for (int e = 0; e < 16; e++) s += FC[i * 16 + e] * sF[j * 16 + e];
            covn[tid] = s;
        }
        if (tid < 8) {
            float s = 0.f;
            #pragma unroll
            for (int e = 0; e < 16; e++) s += sH[tid * 16 + e] * meanp[e];
            out[((size_t)b * MM + tid) * TT + t + 1] = s;
        }
        __syncthreads();
        cov[tid] = covn[tid];
        if (tid < 16) mean[tid] = meanp[tid];
        __syncthreads();
    }
}

extern "C" void kernel_launch(void* const* d_in, const int* in_sizes, int n_in,
                              void* d_out, int out_size) {
    const float* x = (const float*)d_in[0];
    const float* F = (const float*)d_in[1];
    const float* H = (const float*)d_in[2];
    const float* Q = (const float*)d_in[3];
    const float* R = (const float*)d_in[4];
    float* out = (float*)d_out;

    phase1_kernel<<<1, 256>>>(F, H, Q, R);
    group_serial_kernel<<<NCH * 8, 256>>>();
    group_scan_kernel<<<NCH, 256>>>();
    apply_kernel<<<NCH * 7, 256>>>();
    bvec_kernel<<<NCH * (BS / BGB), 256>>>(x);   // also folds NaN detection
    scan_kernel<<<BS / 8, 256>>>();
    phase2b_kernel<<<NCH * (BS / 8), 256>>>(x, out);
    slow_kernel<<<BS, 256>>>(x, F, H, Q, R, out);
}